// round 13
// baseline (speedup 1.0000x reference)
#include <cuda_runtime.h>
#include <cuda_bf16.h>
#include <cstdint>

#define T_STEPS 4096
#define ISZ 1024
#define HSZ 2048
#define OSZ 64
#define NBLK 148
#define RT 256

// ---------------- device scratch (no allocations allowed) -------------------
__device__ float g_xproj[(size_t)T_STEPS * 4 * HSZ];  // [t][gate*H + j]
__device__ unsigned short g_hb[2 * HSZ];              // double-buffered h (bf16)
__device__ __align__(128) unsigned g_flags[160];      // per-block arrival flags
                                                      // [NBLK..159] = UINT_MAX pad
__device__ __align__(128) unsigned g_go_pad[32];      // [0] = broadcast epoch

// ---------------- init: zero h buffers + barrier state ----------------------
__global__ void init_kernel() {
    int i = blockIdx.x * blockDim.x + threadIdx.x;
    int n = blockDim.x * gridDim.x;
    for (int k = i; k < 2 * HSZ; k += n) g_hb[k] = 0;
    for (int k = i; k < 160; k += n) g_flags[k] = (k < NBLK) ? 0u : 0xFFFFFFFFu;
    if (i == 0) g_go_pad[0] = 0u;
}

// ---------------- x-projection GEMM ------------------------------------------
#define BM 128
#define BN 64
#define BK 16

__global__ __launch_bounds__(256) void xproj_kernel(
    const float* __restrict__ A,
    const float* __restrict__ W0, const float* __restrict__ W1,
    const float* __restrict__ W2, const float* __restrict__ W3,
    const float* __restrict__ Wb0, const float* __restrict__ Wb1,
    const float* __restrict__ Wb2, const float* __restrict__ Wb3,
    const float* __restrict__ Ub0, const float* __restrict__ Ub1,
    const float* __restrict__ Ub2, const float* __restrict__ Ub3)
{
    __shared__ float As[BK][BM + 4];
    __shared__ float Bs[BK][BN + 4];
    const int bn = blockIdx.x;
    const int bm = blockIdx.y;
    const int gate = bn >> 5;
    const int j0 = (bn & 31) * BN;
    const float* W  = (gate == 0) ? W0  : (gate == 1) ? W1  : (gate == 2) ? W2  : W3;
    const float* Wb = (gate == 0) ? Wb0 : (gate == 1) ? Wb1 : (gate == 2) ? Wb2 : Wb3;
    const float* Ub = (gate == 0) ? Ub0 : (gate == 1) ? Ub1 : (gate == 2) ? Ub2 : Ub3;
    const int m0 = bm * BM;
    const int tid = threadIdx.x;
    const int tm = tid >> 4, tn = tid & 15;

    float acc[8][4];
#pragma unroll
    for (int i = 0; i < 8; i++)
#pragma unroll
        for (int j = 0; j < 4; j++) acc[i][j] = 0.f;

    for (int k0 = 0; k0 < ISZ; k0 += BK) {
#pragma unroll
        for (int it = 0; it < 2; it++) {
            int e = tid + it * 256;
            int row = e >> 2, kq = e & 3;
            float4 v = *(const float4*)(A + (size_t)(m0 + row) * ISZ + k0 + kq * 4);
            As[kq * 4 + 0][row] = v.x; As[kq * 4 + 1][row] = v.y;
            As[kq * 4 + 2][row] = v.z; As[kq * 4 + 3][row] = v.w;
        }
        {
            int row = tid >> 2, kq = tid & 3;
            float4 v = *(const float4*)(W + (size_t)(j0 + row) * ISZ + k0 + kq * 4);
            Bs[kq * 4 + 0][row] = v.x; Bs[kq * 4 + 1][row] = v.y;
            Bs[kq * 4 + 2][row] = v.z; Bs[kq * 4 + 3][row] = v.w;
        }
        __syncthreads();
#pragma unroll
        for (int k = 0; k < BK; k++) {
            float a[8], bb[4];
#pragma unroll
            for (int i = 0; i < 8; i++) a[i] = As[k][tm * 8 + i];
#pragma unroll
            for (int j = 0; j < 4; j++) bb[j] = Bs[k][tn * 4 + j];
#pragma unroll
            for (int i = 0; i < 8; i++)
#pragma unroll
                for (int j = 0; j < 4; j++)
                    acc[i][j] = fmaf(a[i], bb[j], acc[i][j]);
        }
        __syncthreads();
    }

    float bias[4];
#pragma unroll
    for (int j = 0; j < 4; j++) {
        int col = j0 + tn * 4 + j;
        bias[j] = Wb[col] + Ub[col];
    }
#pragma unroll
    for (int i = 0; i < 8; i++) {
        int row = m0 + tm * 8 + i;
        float4 v = make_float4(acc[i][0] + bias[0], acc[i][1] + bias[1],
                               acc[i][2] + bias[2], acc[i][3] + bias[3]);
        *(float4*)(g_xproj + (size_t)row * (4 * HSZ) + gate * HSZ + j0 + tn * 4) = v;
    }
}

// ---------------- persistent recurrence kernel ------------------------------
#define WS_BYTES (14 * 4 * HSZ * 2)          /* 229376: up to 56 bf16 rows */
#define SMEM_BYTES (WS_BYTES + 512)          /* + gatev[2][64] */

__device__ __forceinline__ float sigm(float x) { return 1.f / (1.f + __expf(-x)); }
__device__ __forceinline__ float tanh_fast(float x) {
    return 1.f - __fdividef(2.f, __expf(2.f * x) + 1.f);
}

// acc.{lo,hi} += {bf16lo(w), bf16hi(w)} * h2.{lo,hi}   (packed fp32 FMA)
__device__ __forceinline__ void bffma2(unsigned long long& acc, unsigned w,
                                       unsigned long long h2) {
    asm("{\n\t"
        ".reg .b32 lo, hi;\n\t"
        ".reg .b64 wf;\n\t"
        "shl.b32 lo, %1, 16;\n\t"
        "and.b32 hi, %1, 0xFFFF0000;\n\t"
        "mov.b64 wf, {lo, hi};\n\t"
        "fma.rn.f32x2 %0, wf, %2, %0;\n\t"
        "}" : "+l"(acc) : "r"(w), "l"(h2));
}
__device__ __forceinline__ unsigned long long bf2f2(unsigned u) {
    unsigned long long r;
    asm("{\n\t"
        ".reg .b32 lo, hi;\n\t"
        "shl.b32 lo, %1, 16;\n\t"
        "and.b32 hi, %1, 0xFFFF0000;\n\t"
        "mov.b64 %0, {lo, hi};\n\t"
        "}" : "=l"(r) : "r"(u));
    return r;
}
__device__ __forceinline__ float2 unpackf2(unsigned long long v) {
    float2 r;
    asm("mov.b64 {%0, %1}, %2;" : "=f"(r.x), "=f"(r.y) : "l"(v));
    return r;
}
__device__ __forceinline__ unsigned ldrelaxed(const unsigned* p) {
    unsigned v;
    asm volatile("ld.relaxed.gpu.global.u32 %0, [%1];" : "=r"(v) : "l"(p));
    return v;
}
__device__ __forceinline__ unsigned ldacq(const unsigned* p) {
    unsigned v;
    asm volatile("ld.acquire.gpu.global.u32 %0, [%1];" : "=r"(v) : "l"(p));
    return v;
}
__device__ __forceinline__ void strel_u32(unsigned* p, unsigned v) {
    asm volatile("st.release.gpu.global.u32 [%0], %1;" :: "l"(p), "r"(v));
}
__device__ __forceinline__ void fence_acqrel() {
    asm volatile("fence.acq_rel.gpu;" ::: "memory");
}
__device__ __forceinline__ void st16cg(unsigned short* p, unsigned short v) {
    asm volatile("st.global.cg.u16 [%0], %1;" :: "l"(p), "h"(v));
}

template<int CNT>
__device__ __forceinline__ void run_steps(char* smem, float* gatev,
                                          int b, int base, int warp, int lane)
{
    const int half = warp & 1;
    const int rbase = warp >> 1;
    const uint4* wb = (const uint4*)(smem + half * 2048) + lane;
    const bool hi16 = (lane & 16) != 0;

    float cst = 0.f;
    float xf = 0.f, xi = 0.f, xc = 0.f, xo = 0.f;
    if (warp == 0 && lane < CNT) {
        const float* xr = g_xproj;
        int j = base + lane;
        xf = __ldg(xr + j);
        xi = __ldg(xr + HSZ + j);
        xc = __ldg(xr + 2 * HSZ + j);
        xo = __ldg(xr + 3 * HSZ + j);
    }

    for (int t = 0; t < T_STEPS; t++) {
        // ---- load this warp's h half (bf16) and unpack to f32x2 ----
        const uint4* hp = (const uint4*)(g_hb + (t & 1) * HSZ + half * 1024) + lane;
        unsigned long long hv[16];
#pragma unroll
        for (int i = 0; i < 4; i++) {
            uint4 v = __ldcg(hp + i * 32);
            hv[4 * i + 0] = bf2f2(v.x);
            hv[4 * i + 1] = bf2f2(v.y);
            hv[4 * i + 2] = bf2f2(v.z);
            hv[4 * i + 3] = bf2f2(v.w);
        }

        // ---- GEMV half-rows, fully unrolled, two rows per iteration ----
#pragma unroll
        for (int m = 0; m + 1 < CNT; m += 2) {
            const int r0 = 4 * m + rbase;
            const int r1 = r0 + 4;
            const uint4* wA = wb + r0 * 256;
            const uint4* wB = wb + r1 * 256;
            unsigned long long accA = 0ull, accB = 0ull;
#pragma unroll
            for (int i = 0; i < 4; i++) {
                uint4 a = wA[i * 32];
                uint4 bq = wB[i * 32];
                bffma2(accA, a.x, hv[4 * i + 0]);
                bffma2(accA, a.y, hv[4 * i + 1]);
                bffma2(accA, a.z, hv[4 * i + 2]);
                bffma2(accA, a.w, hv[4 * i + 3]);
                bffma2(accB, bq.x, hv[4 * i + 0]);
                bffma2(accB, bq.y, hv[4 * i + 1]);
                bffma2(accB, bq.z, hv[4 * i + 2]);
                bffma2(accB, bq.w, hv[4 * i + 3]);
            }
            float2 a2 = unpackf2(accA), b2 = unpackf2(accB);
            float sA = a2.x + a2.y, sB = b2.x + b2.y;
            // paired reduction: fold each across xor-16, then one shared
            // 4-deep chain reduces both rows at once (lane0 -> A, lane16 -> B)
            sA += __shfl_xor_sync(0xffffffffu, sA, 16);
            sB += __shfl_xor_sync(0xffffffffu, sB, 16);
            float v = hi16 ? sB : sA;
#pragma unroll
            for (int o = 8; o > 0; o >>= 1)
                v += __shfl_xor_sync(0xffffffffu, v, o);
            if (lane == 0)  gatev[half * 64 + r0] = v;
            if (lane == 16) gatev[half * 64 + r1] = v;
        }
        if (CNT & 1) {                           // odd tail (CNT = 13)
            const int r0 = 4 * (CNT - 1) + rbase;
            const uint4* wA = wb + r0 * 256;
            unsigned long long accA = 0ull;
#pragma unroll
            for (int i = 0; i < 4; i++) {
                uint4 a = wA[i * 32];
                bffma2(accA, a.x, hv[4 * i + 0]);
                bffma2(accA, a.y, hv[4 * i + 1]);
                bffma2(accA, a.z, hv[4 * i + 2]);
                bffma2(accA, a.w, hv[4 * i + 3]);
            }
            float2 a2 = unpackf2(accA);
            float sA = a2.x + a2.y;
#pragma unroll
            for (int o = 16; o > 0; o >>= 1)
                sA += __shfl_xor_sync(0xffffffffu, sA, o);
            if (lane == 0) gatev[half * 64 + r0] = sA;
        }
        __syncthreads();                         // (A) gatev complete

        // ---- warp 0: cell update, publish h_{t+1}, arrive; detect/broadcast
        if (warp == 0) {
            if (lane < CNT) {
                float f  = sigm(gatev[lane]                + gatev[64 + lane]                + xf);
                float ig = sigm(gatev[CNT + lane]          + gatev[64 + CNT + lane]          + xi);
                float ch = tanh_fast(gatev[2 * CNT + lane] + gatev[64 + 2 * CNT + lane]      + xc);
                float o  = sigm(gatev[3 * CNT + lane]      + gatev[64 + 3 * CNT + lane]      + xo);
                float c  = f * cst + ig * ch;
                cst = c;
                unsigned short hb = __bfloat16_as_ushort(__float2bfloat16_rn(o * tanh_fast(c)));
                st16cg(&g_hb[((t + 1) & 1) * HSZ + base + lane], hb);
            }
            __syncwarp();                        // lanes' h-stores before arrival flag
            if (lane == 0)
                strel_u32(&g_flags[b], (unsigned)(t + 1));  // parallel arrival
            if (lane < CNT && t + 1 < T_STEPS) { // prefetch next x (off hot path)
                const float* xr = g_xproj + (size_t)(t + 1) * (4 * HSZ);
                int j = base + lane;
                xf = __ldg(xr + j);
                xi = __ldg(xr + HSZ + j);
                xc = __ldg(xr + 2 * HSZ + j);
                xo = __ldg(xr + 3 * HSZ + j);
            }
            const unsigned tgt = (unsigned)(t + 1);
            if (b == 0) {
                // ---- sole detector (tiny GEMV -> polling before the field) --
                for (;;) {
                    unsigned m0 = ldrelaxed(g_flags + lane);
                    unsigned m1 = ldrelaxed(g_flags + 32 + lane);
                    unsigned m2 = ldrelaxed(g_flags + 64 + lane);
                    unsigned m3 = ldrelaxed(g_flags + 96 + lane);
                    unsigned m4 = ldrelaxed(g_flags + 128 + lane);
                    unsigned mn = min(min(min(m0, m1), min(m2, m3)), m4);
                    if (__all_sync(0xffffffffu, mn >= tgt)) break;
                }
                fence_acqrel();                  // upgrade observed flags to acquire
                if (lane == 0)
                    strel_u32(&g_go_pad[0], tgt);// broadcast epoch (own line)
            } else if (lane == 0) {
                // ---- 147 pollers on the read-mostly go line ----
                while (ldacq(&g_go_pad[0]) < tgt) { }
            }
        }
        __syncthreads();                         // (B) propagates acquire to all warps
    }
}

__global__ __launch_bounds__(RT, 1) void recur_kernel(
    const float* __restrict__ Uf, const float* __restrict__ Ui,
    const float* __restrict__ Uc, const float* __restrict__ Uo)
{
    extern __shared__ char smem[];
    float* gatev = (float*)(smem + WS_BYTES);   // [2][64] half-partials

    const int b = blockIdx.x;
    const int tid = threadIdx.x;
    const int warp = tid >> 5, lane = tid & 31;
    // block 0: 2 rows (fast detector); blocks 1..135: 14; blocks 136..147: 13
    int cnt, base;
    if (b == 0)        { cnt = 2;  base = 0; }
    else if (b <= 135) { cnt = 14; base = 2 + (b - 1) * 14; }
    else               { cnt = 13; base = 1892 + (b - 136) * 13; }
    const int R = 4 * cnt;

    // ---- stage U rows into SMEM as packed bf16 pairs ----
    {
        const float* Us[4] = {Uf, Ui, Uc, Uo};
        for (int e = tid; e < R * 512; e += RT) {
            int r = e >> 9;
            int c4 = e & 511;
            int g = r / cnt;
            int k = r - g * cnt;
            float4 v = *(const float4*)(Us[g] + (size_t)(base + k) * HSZ + c4 * 4);
            unsigned lo = ((unsigned)__bfloat16_as_ushort(__float2bfloat16_rn(v.y)) << 16)
                        |  (unsigned)__bfloat16_as_ushort(__float2bfloat16_rn(v.x));
            unsigned hi = ((unsigned)__bfloat16_as_ushort(__float2bfloat16_rn(v.w)) << 16)
                        |  (unsigned)__bfloat16_as_ushort(__float2bfloat16_rn(v.z));
            *((uint2*)(smem + (size_t)r * 4096) + c4) = make_uint2(lo, hi);
        }
    }
    __syncthreads();

    if (b == 0)        run_steps<2>(smem, gatev, b, base, warp, lane);
    else if (b <= 135) run_steps<14>(smem, gatev, b, base, warp, lane);
    else               run_steps<13>(smem, gatev, b, base, warp, lane);
}

// ---------------- head: fc + log_softmax over bf16 h ------------------------
__global__ __launch_bounds__(1024) void head_kernel(
    const float* __restrict__ fcw, const float* __restrict__ fcb,
    float* __restrict__ out)
{
    __shared__ float zs[OSZ];
    const int tid = threadIdx.x;
    const int warp = tid >> 5, lane = tid & 31;     // 32 warps, 2 outputs each
    const int o0 = 2 * warp, o1 = o0 + 1;
    const float* w0 = fcw + (size_t)o0 * HSZ;
    const float* w1 = fcw + (size_t)o1 * HSZ;
    float z0 = 0.f, z1 = 0.f;
#pragma unroll
    for (int i = 0; i < 8; i++) {
        int c = i * 256 + lane * 8;
        uint4 hq = *(const uint4*)(g_hb + c);       // 8 bf16 (final h, buf 0)
        float h0 = __uint_as_float(hq.x << 16), h1 = __uint_as_float(hq.x & 0xFFFF0000u);
        float h2 = __uint_as_float(hq.y << 16), h3 = __uint_as_float(hq.y & 0xFFFF0000u);
        float h4 = __uint_as_float(hq.z << 16), h5 = __uint_as_float(hq.z & 0xFFFF0000u);
        float h6 = __uint_as_float(hq.w << 16), h7 = __uint_as_float(hq.w & 0xFFFF0000u);
        float4 a0 = *(const float4*)(w0 + c);
        float4 a1 = *(const float4*)(w0 + c + 4);
        float4 b0 = *(const float4*)(w1 + c);
        float4 b1 = *(const float4*)(w1 + c + 4);
        z0 = fmaf(a0.x, h0, fmaf(a0.y, h1, fmaf(a0.z, h2, fmaf(a0.w, h3, z0))));
        z0 = fmaf(a1.x, h4, fmaf(a1.y, h5, fmaf(a1.z, h6, fmaf(a1.w, h7, z0))));
        z1 = fmaf(b0.x, h0, fmaf(b0.y, h1, fmaf(b0.z, h2, fmaf(b0.w, h3, z1))));
        z1 = fmaf(b1.x, h4, fmaf(b1.y, h5, fmaf(b1.z, h6, fmaf(b1.w, h7, z1))));
    }
#pragma unroll
    for (int o = 16; o > 0; o >>= 1) {
        z0 += __shfl_down_sync(0xffffffffu, z0, o);
        z1 += __shfl_down_sync(0xffffffffu, z1, o);
    }
    if (lane == 0) { zs[o0] = z0 + fcb[o0]; zs[o1] = z1 + fcb[o1]; }
    __syncthreads();
    if (warp == 0) {
        float a = zs[2 * lane], bq = zs[2 * lane + 1];
        float mx = fmaxf(a, bq);
#pragma unroll
        for (int o = 16; o > 0; o >>= 1) mx = fmaxf(mx, __shfl_xor_sync(0xffffffffu, mx, o));
        float s = expf(a - mx) + expf(bq - mx);
#pragma unroll
        for (int o = 16; o > 0; o >>= 1) s += __shfl_xor_sync(0xffffffffu, s, o);
        float lse = mx + logf(s);
        out[2 * lane]     = a - lse;
        out[2 * lane + 1] = bq - lse;
    }
}

// ---------------- launcher ---------------------------------------------------
extern "C" void kernel_launch(void* const* d_in, const int* in_sizes, int n_in,
                              void* d_out, int out_size)
{
    (void)in_sizes; (void)n_in; (void)out_size;
    const float* A    = (const float*)d_in[0];
    const float* Wf_w = (const float*)d_in[1];  const float* Wf_b = (const float*)d_in[2];
    const float* Uf_w = (const float*)d_in[3];  const float* Uf_b = (const float*)d_in[4];
    const float* Wi_w = (const float*)d_in[5];  const float* Wi_b = (const float*)d_in[6];
    const float* Ui_w = (const float*)d_in[7];  const float* Ui_b = (const float*)d_in[8];
    const float* Wc_w = (const float*)d_in[9];  const float* Wc_b = (const float*)d_in[10];
    const float* Uc_w = (const float*)d_in[11]; const float* Uc_b = (const float*)d_in[12];
    const float* Wo_w = (const float*)d_in[13]; const float* Wo_b = (const float*)d_in[14];
    const float* Uo_w = (const float*)d_in[15]; const float* Uo_b = (const float*)d_in[16];
    const float* fc_w = (const float*)d_in[17]; const float* fc_b = (const float*)d_in[18];
    float* out = (float*)d_out;

    cudaFuncSetAttribute(recur_kernel,
                         cudaFuncAttributeMaxDynamicSharedMemorySize, SMEM_BYTES);

    init_kernel<<<32, 256>>>();
    dim3 g(128, 32);
    xproj_kernel<<<g, 256>>>(A, Wf_w, Wi_w, Wc_w, Wo_w,
                             Wf_b, Wi_b, Wc_b, Wo_b,
                             Uf_b, Ui_b, Uc_b, Uo_b);
    recur_kernel<<<NBLK, RT, SMEM_BYTES>>>(Uf_w, Ui_w, Uc_w, Uo_w);
    head_kernel<<<1, 1024>>>(fc_w, fc_b, out);
}

// round 14
// speedup vs baseline: 1.1393x; 1.1393x over previous
#include <cuda_runtime.h>
#include <cuda_bf16.h>
#include <cstdint>

#define T_STEPS 4096
#define ISZ 1024
#define HSZ 2048
#define OSZ 64
#define NBLK 148
#define RT 256

// ---------------- device scratch (no allocations allowed) -------------------
__device__ float g_xproj[(size_t)T_STEPS * 4 * HSZ];  // [t][gate*H + j]
__device__ unsigned short g_hb[2 * HSZ];              // double-buffered h (bf16)
__device__ unsigned g_ctr, g_go;

// ---------------- init: zero h buffers + barrier state ----------------------
__global__ void init_kernel() {
    int i = blockIdx.x * blockDim.x + threadIdx.x;
    int n = blockDim.x * gridDim.x;
    for (int k = i; k < 2 * HSZ; k += n) g_hb[k] = 0;
    if (i == 0) { g_ctr = 0u; g_go = 0u; }
}

// ---------------- x-projection GEMM: tf32 tensor cores -----------------------
// C[t][gate*2048 + j] = A[t,:] . Wg[j,:] + Wg_b[j] + Ug_b[j]
#define XBM 128
#define XBN 128
#define XBK 32
#define XST 136   /* padded SMEM stride: banks (8*tg+g) all distinct */

__device__ __forceinline__ float f2tf32(float x) {
    unsigned r;
    asm("cvt.rna.tf32.f32 %0, %1;" : "=r"(r) : "f"(x));
    return __uint_as_float(r);
}
__device__ __forceinline__ void mma_tf32(float* d, const float* a,
                                         float b0, float b1) {
    asm("mma.sync.aligned.m16n8k8.row.col.f32.tf32.tf32.f32 "
        "{%0,%1,%2,%3}, {%4,%5,%6,%7}, {%8,%9}, {%0,%1,%2,%3};"
        : "+f"(d[0]), "+f"(d[1]), "+f"(d[2]), "+f"(d[3])
        : "r"(__float_as_uint(a[0])), "r"(__float_as_uint(a[1])),
          "r"(__float_as_uint(a[2])), "r"(__float_as_uint(a[3])),
          "r"(__float_as_uint(b0)), "r"(__float_as_uint(b1)));
}

__global__ __launch_bounds__(256, 2) void xproj_tc_kernel(
    const float* __restrict__ A,
    const float* __restrict__ W0, const float* __restrict__ W1,
    const float* __restrict__ W2, const float* __restrict__ W3,
    const float* __restrict__ Wb0, const float* __restrict__ Wb1,
    const float* __restrict__ Wb2, const float* __restrict__ Wb3,
    const float* __restrict__ Ub0, const float* __restrict__ Ub1,
    const float* __restrict__ Ub2, const float* __restrict__ Ub3)
{
    __shared__ float As[XBK][XST];   // [k][m], tf32 bits
    __shared__ float Bs[XBK][XST];   // [k][n]
    const int bn = blockIdx.x;       // 0..63 : gate = bn>>4, 16 n-tiles/gate
    const int bm = blockIdx.y;       // 0..31
    const int gate = bn >> 4;
    const int j0 = (bn & 15) * XBN;
    const float* W  = (gate == 0) ? W0  : (gate == 1) ? W1  : (gate == 2) ? W2  : W3;
    const float* Wb = (gate == 0) ? Wb0 : (gate == 1) ? Wb1 : (gate == 2) ? Wb2 : Wb3;
    const float* Ub = (gate == 0) ? Ub0 : (gate == 1) ? Ub1 : (gate == 2) ? Ub2 : Ub3;
    const int m0 = bm * XBM;
    const int tid = threadIdx.x;
    const int warp = tid >> 5, lane = tid & 31;
    const int g = lane >> 2, tg = lane & 3;
    const int wm = (warp >> 1) * 32;  // warp m offset
    const int wn = (warp & 1) * 64;   // warp n offset
    const int tr = tid >> 3;          // loader row 0..31
    const int tc = (tid & 7) * 4;     // loader k offset

    float acc[2][8][4];
#pragma unroll
    for (int mt = 0; mt < 2; mt++)
#pragma unroll
        for (int nt = 0; nt < 8; nt++)
#pragma unroll
            for (int q = 0; q < 4; q++) acc[mt][nt][q] = 0.f;

    for (int k0 = 0; k0 < ISZ; k0 += XBK) {
#pragma unroll
        for (int p = 0; p < 4; p++) {
            int m = tr + p * 32;
            float4 va = *(const float4*)(A + (size_t)(m0 + m) * ISZ + k0 + tc);
            As[tc + 0][m] = f2tf32(va.x); As[tc + 1][m] = f2tf32(va.y);
            As[tc + 2][m] = f2tf32(va.z); As[tc + 3][m] = f2tf32(va.w);
            float4 vw = *(const float4*)(W + (size_t)(j0 + m) * ISZ + k0 + tc);
            Bs[tc + 0][m] = f2tf32(vw.x); Bs[tc + 1][m] = f2tf32(vw.y);
            Bs[tc + 2][m] = f2tf32(vw.z); Bs[tc + 3][m] = f2tf32(vw.w);
        }
        __syncthreads();
#pragma unroll
        for (int kk = 0; kk < XBK; kk += 8) {
            float a[2][4];
#pragma unroll
            for (int mt = 0; mt < 2; mt++) {
                int mb = wm + mt * 16;
                a[mt][0] = As[kk + tg][mb + g];
                a[mt][1] = As[kk + tg][mb + g + 8];
                a[mt][2] = As[kk + tg + 4][mb + g];
                a[mt][3] = As[kk + tg + 4][mb + g + 8];
            }
#pragma unroll
            for (int nt = 0; nt < 8; nt++) {
                int nb = wn + nt * 8;
                float b0 = Bs[kk + tg][nb + g];
                float b1 = Bs[kk + tg + 4][nb + g];
                mma_tf32(acc[0][nt], a[0], b0, b1);
                mma_tf32(acc[1][nt], a[1], b0, b1);
            }
        }
        __syncthreads();
    }

    // epilogue: bias + store (thread owns cols 2tg,2tg+1 of each n8 tile)
#pragma unroll
    for (int nt = 0; nt < 8; nt++) {
        int jloc = j0 + wn + nt * 8 + 2 * tg;
        float bx = Wb[jloc] + Ub[jloc];
        float by = Wb[jloc + 1] + Ub[jloc + 1];
#pragma unroll
        for (int mt = 0; mt < 2; mt++) {
            int r0 = m0 + wm + mt * 16 + g;
            float* o0 = g_xproj + (size_t)r0 * (4 * HSZ) + gate * HSZ + jloc;
            float* o1 = o0 + 8 * (4 * HSZ);
            *(float2*)o0 = make_float2(acc[mt][nt][0] + bx, acc[mt][nt][1] + by);
            *(float2*)o1 = make_float2(acc[mt][nt][2] + bx, acc[mt][nt][3] + by);
        }
    }
}

// ---------------- persistent recurrence kernel (R5 exact, best 21.1ms) ------
#define WS_BYTES (14 * 4 * HSZ * 2)          /* 229376: up to 56 bf16 rows */
#define SMEM_BYTES (WS_BYTES + 512)          /* + gatev[2][64] */

__device__ __forceinline__ float sigm(float x) { return 1.f / (1.f + __expf(-x)); }
__device__ __forceinline__ float tanh_fast(float x) {
    return 1.f - __fdividef(2.f, __expf(2.f * x) + 1.f);
}

__device__ __forceinline__ void bffma2(unsigned long long& acc, unsigned w,
                                       unsigned long long h2) {
    asm("{\n\t"
        ".reg .b32 lo, hi;\n\t"
        ".reg .b64 wf;\n\t"
        "shl.b32 lo, %1, 16;\n\t"
        "and.b32 hi, %1, 0xFFFF0000;\n\t"
        "mov.b64 wf, {lo, hi};\n\t"
        "fma.rn.f32x2 %0, wf, %2, %0;\n\t"
        "}" : "+l"(acc) : "r"(w), "l"(h2));
}
__device__ __forceinline__ unsigned long long bf2f2(unsigned u) {
    unsigned long long r;
    asm("{\n\t"
        ".reg .b32 lo, hi;\n\t"
        "shl.b32 lo, %1, 16;\n\t"
        "and.b32 hi, %1, 0xFFFF0000;\n\t"
        "mov.b64 %0, {lo, hi};\n\t"
        "}" : "=l"(r) : "r"(u));
    return r;
}
__device__ __forceinline__ float2 unpackf2(unsigned long long v) {
    float2 r;
    asm("mov.b64 {%0, %1}, %2;" : "=f"(r.x), "=f"(r.y) : "l"(v));
    return r;
}
__device__ __forceinline__ unsigned ldacq(const unsigned* p) {
    unsigned v;
    asm volatile("ld.acquire.gpu.u32 %0, [%1];" : "=r"(v) : "l"(p));
    return v;
}
__device__ __forceinline__ unsigned atomrel_add(unsigned* p) {
    unsigned old;
    asm volatile("atom.release.gpu.add.u32 %0, [%1], 1;" : "=r"(old) : "l"(p));
    return old;
}
__device__ __forceinline__ void strel(unsigned* p, unsigned v) {
    asm volatile("st.release.gpu.u32 [%0], %1;" :: "l"(p), "r"(v));
}
__device__ __forceinline__ void st16cg(unsigned short* p, unsigned short v) {
    asm volatile("st.global.cg.u16 [%0], %1;" :: "l"(p), "h"(v));
}

template<int CNT>
__device__ __forceinline__ void run_steps(char* smem, float* gatev,
                                          int base, int warp, int lane)
{
    const int half = warp & 1;
    const int rbase = warp >> 1;
    const uint4* wb = (const uint4*)(smem + half * 2048) + lane;

    float cst = 0.f;
    float xf = 0.f, xi = 0.f, xc = 0.f, xo = 0.f;
    if (warp == 0 && lane < CNT) {
        const float* xr = g_xproj;
        int j = base + lane;
        xf = __ldg(xr + j);
        xi = __ldg(xr + HSZ + j);
        xc = __ldg(xr + 2 * HSZ + j);
        xo = __ldg(xr + 3 * HSZ + j);
    }

    for (int t = 0; t < T_STEPS; t++) {
        const uint4* hp = (const uint4*)(g_hb + (t & 1) * HSZ + half * 1024) + lane;
        unsigned long long hv[16];
#pragma unroll
        for (int i = 0; i < 4; i++) {
            uint4 v = __ldcg(hp + i * 32);
            hv[4 * i + 0] = bf2f2(v.x);
            hv[4 * i + 1] = bf2f2(v.y);
            hv[4 * i + 2] = bf2f2(v.z);
            hv[4 * i + 3] = bf2f2(v.w);
        }

#pragma unroll
        for (int m = 0; m + 1 < CNT; m += 2) {
            const int r0 = 4 * m + rbase;
            const int r1 = r0 + 4;
            const uint4* wA = wb + r0 * 256;
            const uint4* wB = wb + r1 * 256;
            unsigned long long accA = 0ull, accB = 0ull;
#pragma unroll
            for (int i = 0; i < 4; i++) {
                uint4 a = wA[i * 32];
                uint4 bq = wB[i * 32];
                bffma2(accA, a.x, hv[4 * i + 0]);
                bffma2(accA, a.y, hv[4 * i + 1]);
                bffma2(accA, a.z, hv[4 * i + 2]);
                bffma2(accA, a.w, hv[4 * i + 3]);
                bffma2(accB, bq.x, hv[4 * i + 0]);
                bffma2(accB, bq.y, hv[4 * i + 1]);
                bffma2(accB, bq.z, hv[4 * i + 2]);
                bffma2(accB, bq.w, hv[4 * i + 3]);
            }
            float2 a2 = unpackf2(accA), b2 = unpackf2(accB);
            float sA = a2.x + a2.y, sB = b2.x + b2.y;
#pragma unroll
            for (int o = 16; o > 0; o >>= 1) {
                sA += __shfl_down_sync(0xffffffffu, sA, o);
                sB += __shfl_down_sync(0xffffffffu, sB, o);
            }
            if (lane == 0) {
                gatev[half * 64 + r0] = sA;
                gatev[half * 64 + r1] = sB;
            }
        }
        if (CNT & 1) {                           // odd tail (CNT = 13)
            const int r0 = 4 * (CNT - 1) + rbase;
            const uint4* wA = wb + r0 * 256;
            unsigned long long accA = 0ull;
#pragma unroll
            for (int i = 0; i < 4; i++) {
                uint4 a = wA[i * 32];
                bffma2(accA, a.x, hv[4 * i + 0]);
                bffma2(accA, a.y, hv[4 * i + 1]);
                bffma2(accA, a.z, hv[4 * i + 2]);
                bffma2(accA, a.w, hv[4 * i + 3]);
            }
            float2 a2 = unpackf2(accA);
            float sA = a2.x + a2.y;
#pragma unroll
            for (int o = 16; o > 0; o >>= 1)
                sA += __shfl_down_sync(0xffffffffu, sA, o);
            if (lane == 0) gatev[half * 64 + r0] = sA;
        }
        __syncthreads();                         // (A) gatev complete

        if (warp == 0) {
            if (lane < CNT) {
                float f  = sigm(gatev[lane]                + gatev[64 + lane]                + xf);
                float ig = sigm(gatev[CNT + lane]          + gatev[64 + CNT + lane]          + xi);
                float ch = tanh_fast(gatev[2 * CNT + lane] + gatev[64 + 2 * CNT + lane]      + xc);
                float o  = sigm(gatev[3 * CNT + lane]      + gatev[64 + 3 * CNT + lane]      + xo);
                float c  = f * cst + ig * ch;
                cst = c;
                unsigned short hb = __bfloat16_as_ushort(__float2bfloat16_rn(o * tanh_fast(c)));
                st16cg(&g_hb[((t + 1) & 1) * HSZ + base + lane], hb);
            }
            __syncwarp();
            unsigned old = 0;
            if (lane == 0) {
                __threadfence();
                old = atomrel_add(&g_ctr);
                if (old == (unsigned)t * NBLK + (NBLK - 1))
                    strel(&g_go, (unsigned)(t + 1));
            }
            if (lane < CNT && t + 1 < T_STEPS) {
                const float* xr = g_xproj + (size_t)(t + 1) * (4 * HSZ);
                int j = base + lane;
                xf = __ldg(xr + j);
                xi = __ldg(xr + HSZ + j);
                xc = __ldg(xr + 2 * HSZ + j);
                xo = __ldg(xr + 3 * HSZ + j);
            }
            if (lane == 0) {
                while (ldacq(&g_go) < (unsigned)(t + 1)) { }
            }
        }
        __syncthreads();                         // (B) h_{t+1} visible
    }
}

__global__ __launch_bounds__(RT, 1) void recur_kernel(
    const float* __restrict__ Uf, const float* __restrict__ Ui,
    const float* __restrict__ Uc, const float* __restrict__ Uo)
{
    extern __shared__ char smem[];
    float* gatev = (float*)(smem + WS_BYTES);

    const int b = blockIdx.x;
    const int tid = threadIdx.x;
    const int warp = tid >> 5, lane = tid & 31;
    const int cnt  = (b < 124) ? 14 : 13;
    const int base = b * 13 + ((b < 124) ? b : 124);
    const int R = 4 * cnt;

    {
        const float* Us[4] = {Uf, Ui, Uc, Uo};
        for (int e = tid; e < R * 512; e += RT) {
            int r = e >> 9;
            int c4 = e & 511;
            int g = r / cnt;
            int k = r - g * cnt;
            float4 v = *(const float4*)(Us[g] + (size_t)(base + k) * HSZ + c4 * 4);
            unsigned lo = ((unsigned)__bfloat16_as_ushort(__float2bfloat16_rn(v.y)) << 16)
                        |  (unsigned)__bfloat16_as_ushort(__float2bfloat16_rn(v.x));
            unsigned hi = ((unsigned)__bfloat16_as_ushort(__float2bfloat16_rn(v.w)) << 16)
                        |  (unsigned)__bfloat16_as_ushort(__float2bfloat16_rn(v.z));
            *((uint2*)(smem + (size_t)r * 4096) + c4) = make_uint2(lo, hi);
        }
    }
    __syncthreads();

    if (cnt == 14) run_steps<14>(smem, gatev, base, warp, lane);
    else           run_steps<13>(smem, gatev, base, warp, lane);
}

// ---------------- head: fc + log_softmax over bf16 h ------------------------
__global__ __launch_bounds__(1024) void head_kernel(
    const float* __restrict__ fcw, const float* __restrict__ fcb,
    float* __restrict__ out)
{
    __shared__ float zs[OSZ];
    const int tid = threadIdx.x;
    const int warp = tid >> 5, lane = tid & 31;
    const int o0 = 2 * warp, o1 = o0 + 1;
    const float* w0 = fcw + (size_t)o0 * HSZ;
    const float* w1 = fcw + (size_t)o1 * HSZ;
    float z0 = 0.f, z1 = 0.f;
#pragma unroll
    for (int i = 0; i < 8; i++) {
        int c = i * 256 + lane * 8;
        uint4 hq = *(const uint4*)(g_hb + c);
        float h0 = __uint_as_float(hq.x << 16), h1 = __uint_as_float(hq.x & 0xFFFF0000u);
        float h2 = __uint_as_float(hq.y << 16), h3 = __uint_as_float(hq.y & 0xFFFF0000u);
        float h4 = __uint_as_float(hq.z << 16), h5 = __uint_as_float(hq.z & 0xFFFF0000u);
        float h6 = __uint_as_float(hq.w << 16), h7 = __uint_as_float(hq.w & 0xFFFF0000u);
        float4 a0 = *(const float4*)(w0 + c);
        float4 a1 = *(const float4*)(w0 + c + 4);
        float4 b0 = *(const float4*)(w1 + c);
        float4 b1 = *(const float4*)(w1 + c + 4);
        z0 = fmaf(a0.x, h0, fmaf(a0.y, h1, fmaf(a0.z, h2, fmaf(a0.w, h3, z0))));
        z0 = fmaf(a1.x, h4, fmaf(a1.y, h5, fmaf(a1.z, h6, fmaf(a1.w, h7, z0))));
        z1 = fmaf(b0.x, h0, fmaf(b0.y, h1, fmaf(b0.z, h2, fmaf(b0.w, h3, z1))));
        z1 = fmaf(b1.x, h4, fmaf(b1.y, h5, fmaf(b1.z, h6, fmaf(b1.w, h7, z1))));
    }
#pragma unroll
    for (int o = 16; o > 0; o >>= 1) {
        z0 += __shfl_down_sync(0xffffffffu, z0, o);
        z1 += __shfl_down_sync(0xffffffffu, z1, o);
    }
    if (lane == 0) { zs[o0] = z0 + fcb[o0]; zs[o1] = z1 + fcb[o1]; }
    __syncthreads();
    if (warp == 0) {
        float a = zs[2 * lane], bq = zs[2 * lane + 1];
        float mx = fmaxf(a, bq);
#pragma unroll
        for (int o = 16; o > 0; o >>= 1) mx = fmaxf(mx, __shfl_xor_sync(0xffffffffu, mx, o));
        float s = expf(a - mx) + expf(bq - mx);
#pragma unroll
        for (int o = 16; o > 0; o >>= 1) s += __shfl_xor_sync(0xffffffffu, s, o);
        float lse = mx + logf(s);
        out[2 * lane]     = a - lse;
        out[2 * lane + 1] = bq - lse;
    }
}

// ---------------- launcher ---------------------------------------------------
extern "C" void kernel_launch(void* const* d_in, const int* in_sizes, int n_in,
                              void* d_out, int out_size)
{
    (void)in_sizes; (void)n_in; (void)out_size;
    const float* A    = (const float*)d_in[0];
    const float* Wf_w = (const float*)d_in[1];  const float* Wf_b = (const float*)d_in[2];
    const float* Uf_w = (const float*)d_in[3];  const float* Uf_b = (const float*)d_in[4];
    const float* Wi_w = (const float*)d_in[5];  const float* Wi_b = (const float*)d_in[6];
    const float* Ui_w = (const float*)d_in[7];  const float* Ui_b = (const float*)d_in[8];
    const float* Wc_w = (const float*)d_in[9];  const float* Wc_b = (const float*)d_in[10];
    const float* Uc_w = (const float*)d_in[11]; const float* Uc_b = (const float*)d_in[12];
    const float* Wo_w = (const float*)d_in[13]; const float* Wo_b = (const float*)d_in[14];
    const float* Uo_w = (const float*)d_in[15]; const float* Uo_b = (const float*)d_in[16];
    const float* fc_w = (const float*)d_in[17]; const float* fc_b = (const float*)d_in[18];
    float* out = (float*)d_out;

    cudaFuncSetAttribute(recur_kernel,
                         cudaFuncAttributeMaxDynamicSharedMemorySize, SMEM_BYTES);

    init_kernel<<<16, 256>>>();
    dim3 g(64, 32);
    xproj_tc_kernel<<<g, 256>>>(A, Wf_w, Wi_w, Wc_w, Wo_w,
                                Wf_b, Wi_b, Wc_b, Wo_b,
                                Uf_b, Ui_b, Uc_b, Uo_b);
    recur_kernel<<<NBLK, RT, SMEM_BYTES>>>(Uf_w, Ui_w, Uc_w, Uo_w);
    head_kernel<<<1, 1024>>>(fc_w, fc_b, out);
}

// round 15
// speedup vs baseline: 1.2524x; 1.0992x over previous
#include <cuda_runtime.h>
#include <cuda_bf16.h>
#include <cstdint>

#define T_STEPS 4096
#define ISZ 1024
#define HSZ 2048
#define OSZ 64
#define NBLK 148
#define RT 256

// ---------------- device scratch (no allocations allowed) -------------------
__device__ float g_xproj[(size_t)T_STEPS * 4 * HSZ];  // [t][gate*H + j]
__device__ unsigned short g_hb[2 * HSZ];              // double-buffered h (bf16)
__device__ unsigned g_ctr, g_go;

// ---------------- init: zero h buffers + barrier state ----------------------
__global__ void init_kernel() {
    int i = blockIdx.x * blockDim.x + threadIdx.x;
    int n = blockDim.x * gridDim.x;
    for (int k = i; k < 2 * HSZ; k += n) g_hb[k] = 0;
    if (i == 0) { g_ctr = 0u; g_go = 0u; }
}

// ---------------- x-projection GEMM: tf32 tensor cores (R14, won) ------------
#define XBM 128
#define XBN 128
#define XBK 32
#define XST 136

__device__ __forceinline__ float f2tf32(float x) {
    unsigned r;
    asm("cvt.rna.tf32.f32 %0, %1;" : "=r"(r) : "f"(x));
    return __uint_as_float(r);
}
__device__ __forceinline__ void mma_tf32(float* d, const float* a,
                                         float b0, float b1) {
    asm("mma.sync.aligned.m16n8k8.row.col.f32.tf32.tf32.f32 "
        "{%0,%1,%2,%3}, {%4,%5,%6,%7}, {%8,%9}, {%0,%1,%2,%3};"
        : "+f"(d[0]), "+f"(d[1]), "+f"(d[2]), "+f"(d[3])
        : "r"(__float_as_uint(a[0])), "r"(__float_as_uint(a[1])),
          "r"(__float_as_uint(a[2])), "r"(__float_as_uint(a[3])),
          "r"(__float_as_uint(b0)), "r"(__float_as_uint(b1)));
}

__global__ __launch_bounds__(256, 2) void xproj_tc_kernel(
    const float* __restrict__ A,
    const float* __restrict__ W0, const float* __restrict__ W1,
    const float* __restrict__ W2, const float* __restrict__ W3,
    const float* __restrict__ Wb0, const float* __restrict__ Wb1,
    const float* __restrict__ Wb2, const float* __restrict__ Wb3,
    const float* __restrict__ Ub0, const float* __restrict__ Ub1,
    const float* __restrict__ Ub2, const float* __restrict__ Ub3)
{
    __shared__ float As[XBK][XST];
    __shared__ float Bs[XBK][XST];
    const int bn = blockIdx.x;
    const int bm = blockIdx.y;
    const int gate = bn >> 4;
    const int j0 = (bn & 15) * XBN;
    const float* W  = (gate == 0) ? W0  : (gate == 1) ? W1  : (gate == 2) ? W2  : W3;
    const float* Wb = (gate == 0) ? Wb0 : (gate == 1) ? Wb1 : (gate == 2) ? Wb2 : Wb3;
    const float* Ub = (gate == 0) ? Ub0 : (gate == 1) ? Ub1 : (gate == 2) ? Ub2 : Ub3;
    const int m0 = bm * XBM;
    const int tid = threadIdx.x;
    const int warp = tid >> 5, lane = tid & 31;
    const int g = lane >> 2, tg = lane & 3;
    const int wm = (warp >> 1) * 32;
    const int wn = (warp & 1) * 64;
    const int tr = tid >> 3;
    const int tc = (tid & 7) * 4;

    float acc[2][8][4];
#pragma unroll
    for (int mt = 0; mt < 2; mt++)
#pragma unroll
        for (int nt = 0; nt < 8; nt++)
#pragma unroll
            for (int q = 0; q < 4; q++) acc[mt][nt][q] = 0.f;

    for (int k0 = 0; k0 < ISZ; k0 += XBK) {
#pragma unroll
        for (int p = 0; p < 4; p++) {
            int m = tr + p * 32;
            float4 va = *(const float4*)(A + (size_t)(m0 + m) * ISZ + k0 + tc);
            As[tc + 0][m] = f2tf32(va.x); As[tc + 1][m] = f2tf32(va.y);
            As[tc + 2][m] = f2tf32(va.z); As[tc + 3][m] = f2tf32(va.w);
            float4 vw = *(const float4*)(W + (size_t)(j0 + m) * ISZ + k0 + tc);
            Bs[tc + 0][m] = f2tf32(vw.x); Bs[tc + 1][m] = f2tf32(vw.y);
            Bs[tc + 2][m] = f2tf32(vw.z); Bs[tc + 3][m] = f2tf32(vw.w);
        }
        __syncthreads();
#pragma unroll
        for (int kk = 0; kk < XBK; kk += 8) {
            float a[2][4];
#pragma unroll
            for (int mt = 0; mt < 2; mt++) {
                int mb = wm + mt * 16;
                a[mt][0] = As[kk + tg][mb + g];
                a[mt][1] = As[kk + tg][mb + g + 8];
                a[mt][2] = As[kk + tg + 4][mb + g];
                a[mt][3] = As[kk + tg + 4][mb + g + 8];
            }
#pragma unroll
            for (int nt = 0; nt < 8; nt++) {
                int nb = wn + nt * 8;
                float b0 = Bs[kk + tg][nb + g];
                float b1 = Bs[kk + tg + 4][nb + g];
                mma_tf32(acc[0][nt], a[0], b0, b1);
                mma_tf32(acc[1][nt], a[1], b0, b1);
            }
        }
        __syncthreads();
    }

#pragma unroll
    for (int nt = 0; nt < 8; nt++) {
        int jloc = j0 + wn + nt * 8 + 2 * tg;
        float bx = Wb[jloc] + Ub[jloc];
        float by = Wb[jloc + 1] + Ub[jloc + 1];
#pragma unroll
        for (int mt = 0; mt < 2; mt++) {
            int r0 = m0 + wm + mt * 16 + g;
            float* o0 = g_xproj + (size_t)r0 * (4 * HSZ) + gate * HSZ + jloc;
            float* o1 = o0 + 8 * (4 * HSZ);
            *(float2*)o0 = make_float2(acc[mt][nt][0] + bx, acc[mt][nt][1] + by);
            *(float2*)o1 = make_float2(acc[mt][nt][2] + bx, acc[mt][nt][3] + by);
        }
    }
}

// ---------------- persistent recurrence kernel ------------------------------
#define WS_BYTES (14 * 4 * HSZ * 2)          /* 229376: up to 56 bf16 rows */
#define SMEM_BYTES (WS_BYTES + 512)          /* + gatev[2][64] */

__device__ __forceinline__ float sigm(float x) { return 1.f / (1.f + __expf(-x)); }
__device__ __forceinline__ float tanh_fast(float x) {
    return 1.f - __fdividef(2.f, __expf(2.f * x) + 1.f);
}

__device__ __forceinline__ void bffma2(unsigned long long& acc, unsigned w,
                                       unsigned long long h2) {
    asm("{\n\t"
        ".reg .b32 lo, hi;\n\t"
        ".reg .b64 wf;\n\t"
        "shl.b32 lo, %1, 16;\n\t"
        "and.b32 hi, %1, 0xFFFF0000;\n\t"
        "mov.b64 wf, {lo, hi};\n\t"
        "fma.rn.f32x2 %0, wf, %2, %0;\n\t"
        "}" : "+l"(acc) : "r"(w), "l"(h2));
}
__device__ __forceinline__ unsigned long long bf2f2(unsigned u) {
    unsigned long long r;
    asm("{\n\t"
        ".reg .b32 lo, hi;\n\t"
        "shl.b32 lo, %1, 16;\n\t"
        "and.b32 hi, %1, 0xFFFF0000;\n\t"
        "mov.b64 %0, {lo, hi};\n\t"
        "}" : "=l"(r) : "r"(u));
    return r;
}
__device__ __forceinline__ float2 unpackf2(unsigned long long v) {
    float2 r;
    asm("mov.b64 {%0, %1}, %2;" : "=f"(r.x), "=f"(r.y) : "l"(v));
    return r;
}
__device__ __forceinline__ unsigned ldacq(const unsigned* p) {
    unsigned v;
    asm volatile("ld.acquire.gpu.u32 %0, [%1];" : "=r"(v) : "l"(p));
    return v;
}
__device__ __forceinline__ unsigned atomrel_add(unsigned* p) {
    unsigned old;
    asm volatile("atom.release.gpu.add.u32 %0, [%1], 1;" : "=r"(old) : "l"(p));
    return old;
}
__device__ __forceinline__ void strel(unsigned* p, unsigned v) {
    asm volatile("st.release.gpu.u32 [%0], %1;" :: "l"(p), "r"(v));
}
__device__ __forceinline__ void st16cg(unsigned short* p, unsigned short v) {
    asm volatile("st.global.cg.u16 [%0], %1;" :: "l"(p), "h"(v));
}

template<int CNT>
__device__ __forceinline__ void run_steps(char* smem, float* gatev,
                                          int base, int warp, int lane)
{
    const int half = warp & 1;
    const int rbase = warp >> 1;
    const uint4* wb = (const uint4*)(smem + half * 2048) + lane;

    // ---- register-resident weights: second row of each GEMV pair ----
    constexpr int NPAIR = CNT >> 1;              // 7 (CNT=14) or 6 (CNT=13)
    uint4 wreg[NPAIR][4];                        // NPAIR*16 u32 regs/thread
#pragma unroll
    for (int p = 0; p < NPAIR; p++) {
        const int r1 = 8 * p + 4 + rbase;
        const uint4* src = wb + r1 * 256;
#pragma unroll
        for (int i = 0; i < 4; i++) wreg[p][i] = src[i * 32];
    }

    float cst = 0.f;
    float xf = 0.f, xi = 0.f, xc = 0.f, xo = 0.f;
    if (warp == 0 && lane < CNT) {
        const float* xr = g_xproj;
        int j = base + lane;
        xf = __ldg(xr + j);
        xi = __ldg(xr + HSZ + j);
        xc = __ldg(xr + 2 * HSZ + j);
        xo = __ldg(xr + 3 * HSZ + j);
    }

    for (int t = 0; t < T_STEPS; t++) {
        const uint4* hp = (const uint4*)(g_hb + (t & 1) * HSZ + half * 1024) + lane;
        unsigned long long hv[16];
#pragma unroll
        for (int i = 0; i < 4; i++) {
            uint4 v = __ldcg(hp + i * 32);
            hv[4 * i + 0] = bf2f2(v.x);
            hv[4 * i + 1] = bf2f2(v.y);
            hv[4 * i + 2] = bf2f2(v.z);
            hv[4 * i + 3] = bf2f2(v.w);
        }

        // ---- GEMV: row A from SMEM, row B from registers ----
#pragma unroll
        for (int p = 0; p < NPAIR; p++) {
            const int r0 = 8 * p + rbase;
            const int r1 = r0 + 4;
            const uint4* wA = wb + r0 * 256;
            unsigned long long accA = 0ull, accB = 0ull;
#pragma unroll
            for (int i = 0; i < 4; i++) {
                uint4 a = wA[i * 32];
                uint4 bq = wreg[p][i];
                bffma2(accA, a.x, hv[4 * i + 0]);
                bffma2(accA, a.y, hv[4 * i + 1]);
                bffma2(accA, a.z, hv[4 * i + 2]);
                bffma2(accA, a.w, hv[4 * i + 3]);
                bffma2(accB, bq.x, hv[4 * i + 0]);
                bffma2(accB, bq.y, hv[4 * i + 1]);
                bffma2(accB, bq.z, hv[4 * i + 2]);
                bffma2(accB, bq.w, hv[4 * i + 3]);
            }
            float2 a2 = unpackf2(accA), b2 = unpackf2(accB);
            float sA = a2.x + a2.y, sB = b2.x + b2.y;
#pragma unroll
            for (int o = 16; o > 0; o >>= 1) {
                sA += __shfl_down_sync(0xffffffffu, sA, o);
                sB += __shfl_down_sync(0xffffffffu, sB, o);
            }
            if (lane == 0) {
                gatev[half * 64 + r0] = sA;
                gatev[half * 64 + r1] = sB;
            }
        }
        if (CNT & 1) {                           // odd tail (CNT = 13)
            const int r0 = 4 * (CNT - 1) + rbase;
            const uint4* wA = wb + r0 * 256;
            unsigned long long accA = 0ull;
#pragma unroll
            for (int i = 0; i < 4; i++) {
                uint4 a = wA[i * 32];
                bffma2(accA, a.x, hv[4 * i + 0]);
                bffma2(accA, a.y, hv[4 * i + 1]);
                bffma2(accA, a.z, hv[4 * i + 2]);
                bffma2(accA, a.w, hv[4 * i + 3]);
            }
            float2 a2 = unpackf2(accA);
            float sA = a2.x + a2.y;
#pragma unroll
            for (int o = 16; o > 0; o >>= 1)
                sA += __shfl_down_sync(0xffffffffu, sA, o);
            if (lane == 0) gatev[half * 64 + r0] = sA;
        }
        __syncthreads();                         // (A) gatev complete

        if (warp == 0) {
            if (lane < CNT) {
                float f  = sigm(gatev[lane]                + gatev[64 + lane]                + xf);
                float ig = sigm(gatev[CNT + lane]          + gatev[64 + CNT + lane]          + xi);
                float ch = tanh_fast(gatev[2 * CNT + lane] + gatev[64 + 2 * CNT + lane]      + xc);
                float o  = sigm(gatev[3 * CNT + lane]      + gatev[64 + 3 * CNT + lane]      + xo);
                float c  = f * cst + ig * ch;
                cst = c;
                unsigned short hb = __bfloat16_as_ushort(__float2bfloat16_rn(o * tanh_fast(c)));
                st16cg(&g_hb[((t + 1) & 1) * HSZ + base + lane], hb);
            }
            __syncwarp();                        // lanes' stores ordered, then release
            unsigned old = 0;
            if (lane == 0) {
                old = atomrel_add(&g_ctr);       // no threadfence: release atomic
                if (old == (unsigned)t * NBLK + (NBLK - 1))
                    strel(&g_go, (unsigned)(t + 1));
            }
            if (lane < CNT && t + 1 < T_STEPS) {
                const float* xr = g_xproj + (size_t)(t + 1) * (4 * HSZ);
                int j = base + lane;
                xf = __ldg(xr + j);
                xi = __ldg(xr + HSZ + j);
                xc = __ldg(xr + 2 * HSZ + j);
                xo = __ldg(xr + 3 * HSZ + j);
            }
            if (lane == 0) {
                while (ldacq(&g_go) < (unsigned)(t + 1)) { }
            }
        }
        __syncthreads();                         // (B) h_{t+1} visible
    }
}

__global__ __launch_bounds__(RT, 1) void recur_kernel(
    const float* __restrict__ Uf, const float* __restrict__ Ui,
    const float* __restrict__ Uc, const float* __restrict__ Uo)
{
    extern __shared__ char smem[];
    float* gatev = (float*)(smem + WS_BYTES);

    const int b = blockIdx.x;
    const int tid = threadIdx.x;
    const int warp = tid >> 5, lane = tid & 31;
    const int cnt  = (b < 124) ? 14 : 13;
    const int base = b * 13 + ((b < 124) ? b : 124);
    const int R = 4 * cnt;

    {
        const float* Us[4] = {Uf, Ui, Uc, Uo};
        for (int e = tid; e < R * 512; e += RT) {
            int r = e >> 9;
            int c4 = e & 511;
            int g = r / cnt;
            int k = r - g * cnt;
            float4 v = *(const float4*)(Us[g] + (size_t)(base + k) * HSZ + c4 * 4);
            unsigned lo = ((unsigned)__bfloat16_as_ushort(__float2bfloat16_rn(v.y)) << 16)
                        |  (unsigned)__bfloat16_as_ushort(__float2bfloat16_rn(v.x));
            unsigned hi = ((unsigned)__bfloat16_as_ushort(__float2bfloat16_rn(v.w)) << 16)
                        |  (unsigned)__bfloat16_as_ushort(__float2bfloat16_rn(v.z));
            *((uint2*)(smem + (size_t)r * 4096) + c4) = make_uint2(lo, hi);
        }
    }
    __syncthreads();

    if (cnt == 14) run_steps<14>(smem, gatev, base, warp, lane);
    else           run_steps<13>(smem, gatev, base, warp, lane);
}

// ---------------- head: fc + log_softmax over bf16 h ------------------------
__global__ __launch_bounds__(1024) void head_kernel(
    const float* __restrict__ fcw, const float* __restrict__ fcb,
    float* __restrict__ out)
{
    __shared__ float zs[OSZ];
    const int tid = threadIdx.x;
    const int warp = tid >> 5, lane = tid & 31;
    const int o0 = 2 * warp, o1 = o0 + 1;
    const float* w0 = fcw + (size_t)o0 * HSZ;
    const float* w1 = fcw + (size_t)o1 * HSZ;
    float z0 = 0.f, z1 = 0.f;
#pragma unroll
    for (int i = 0; i < 8; i++) {
        int c = i * 256 + lane * 8;
        uint4 hq = *(const uint4*)(g_hb + c);
        float h0 = __uint_as_float(hq.x << 16), h1 = __uint_as_float(hq.x & 0xFFFF0000u);
        float h2 = __uint_as_float(hq.y << 16), h3 = __uint_as_float(hq.y & 0xFFFF0000u);
        float h4 = __uint_as_float(hq.z << 16), h5 = __uint_as_float(hq.z & 0xFFFF0000u);
        float h6 = __uint_as_float(hq.w << 16), h7 = __uint_as_float(hq.w & 0xFFFF0000u);
        float4 a0 = *(const float4*)(w0 + c);
        float4 a1 = *(const float4*)(w0 + c + 4);
        float4 b0 = *(const float4*)(w1 + c);
        float4 b1 = *(const float4*)(w1 + c + 4);
        z0 = fmaf(a0.x, h0, fmaf(a0.y, h1, fmaf(a0.z, h2, fmaf(a0.w, h3, z0))));
        z0 = fmaf(a1.x, h4, fmaf(a1.y, h5, fmaf(a1.z, h6, fmaf(a1.w, h7, z0))));
        z1 = fmaf(b0.x, h0, fmaf(b0.y, h1, fmaf(b0.z, h2, fmaf(b0.w, h3, z1))));
        z1 = fmaf(b1.x, h4, fmaf(b1.y, h5, fmaf(b1.z, h6, fmaf(b1.w, h7, z1))));
    }
#pragma unroll
    for (int o = 16; o > 0; o >>= 1) {
        z0 += __shfl_down_sync(0xffffffffu, z0, o);
        z1 += __shfl_down_sync(0xffffffffu, z1, o);
    }
    if (lane == 0) { zs[o0] = z0 + fcb[o0]; zs[o1] = z1 + fcb[o1]; }
    __syncthreads();
    if (warp == 0) {
        float a = zs[2 * lane], bq = zs[2 * lane + 1];
        float mx = fmaxf(a, bq);
#pragma unroll
        for (int o = 16; o > 0; o >>= 1) mx = fmaxf(mx, __shfl_xor_sync(0xffffffffu, mx, o));
        float s = expf(a - mx) + expf(bq - mx);
#pragma unroll
        for (int o = 16; o > 0; o >>= 1) s += __shfl_xor_sync(0xffffffffu, s, o);
        float lse = mx + logf(s);
        out[2 * lane]     = a - lse;
        out[2 * lane + 1] = bq - lse;
    }
}

// ---------------- launcher ---------------------------------------------------
extern "C" void kernel_launch(void* const* d_in, const int* in_sizes, int n_in,
                              void* d_out, int out_size)
{
    (void)in_sizes; (void)n_in; (void)out_size;
    const float* A    = (const float*)d_in[0];
    const float* Wf_w = (const float*)d_in[1];  const float* Wf_b = (const float*)d_in[2];
    const float* Uf_w = (const float*)d_in[3];  const float* Uf_b = (const float*)d_in[4];
    const float* Wi_w = (const float*)d_in[5];  const float* Wi_b = (const float*)d_in[6];
    const float* Ui_w = (const float*)d_in[7];  const float* Ui_b = (const float*)d_in[8];
    const float* Wc_w = (const float*)d_in[9];  const float* Wc_b = (const float*)d_in[10];
    const float* Uc_w = (const float*)d_in[11]; const float* Uc_b = (const float*)d_in[12];
    const float* Wo_w = (const float*)d_in[13]; const float* Wo_b = (const float*)d_in[14];
    const float* Uo_w = (const float*)d_in[15]; const float* Uo_b = (const float*)d_in[16];
    const float* fc_w = (const float*)d_in[17]; const float* fc_b = (const float*)d_in[18];
    float* out = (float*)d_out;

    cudaFuncSetAttribute(recur_kernel,
                         cudaFuncAttributeMaxDynamicSharedMemorySize, SMEM_BYTES);

    init_kernel<<<16, 256>>>();
    dim3 g(64, 32);
    xproj_tc_kernel<<<g, 256>>>(A, Wf_w, Wi_w, Wc_w, Wo_w,
                                Wf_b, Wi_b, Wc_b, Wo_b,
                                Uf_b, Ui_b, Uc_b, Uo_b);
    recur_kernel<<<NBLK, RT, SMEM_BYTES>>>(Uf_w, Ui_w, Uc_w, Uo_w);
    head_kernel<<<1, 1024>>>(fc_w, fc_b, out);
}